// round 1
// baseline (speedup 1.0000x reference)
#include <cuda_runtime.h>

// PairwiseMamba: 2304 independent Mamba sequences (T=1024, d_inner=4, d_state=8)
// One warp per sequence; lane = (d,s). Fully fused register-resident scan.
// Post-scan linearity folded into per-lane accumulators (acc, sacc).

#define NSEQ  2304
#define TLEN  1024
#define WPB   8          // warps per block
#define BLOCK (WPB * 32)
#define CHUNK 64         // timesteps staged in smem per refill

__global__ void zero_out_kernel(float* out, int n) {
    int i = blockIdx.x * blockDim.x + threadIdx.x;
    if (i < n) out[i] = 0.f;
}

__device__ __forceinline__ float fast_sigmoid(float x) {
    // 1 / (1 + exp(-x)) via MUFU EX2 + RCP (~2 ulp)
    return __fdividef(1.0f, 1.0f + __expf(-x));
}

__global__ __launch_bounds__(BLOCK) void mamba_fused_kernel(
    const float* __restrict__ raw,    // (B,W,P,2,T) = (2304, 2, 1024)
    const float* __restrict__ ipw,    // (8,2)   in_proj_w
    const float* __restrict__ cw,     // (4,2)   conv_w
    const float* __restrict__ cb,     // (4,)    conv_b
    const float* __restrict__ xpw,    // (17,4)  x_proj_w
    const float* __restrict__ dtw_,   // (4,1)   dt_proj_w
    const float* __restrict__ dtb_,   // (4,)    dt_proj_b
    const float* __restrict__ Alog,   // (4,8)   A_log
    const float* __restrict__ Dskip,  // (4,)
    const float* __restrict__ outw,   // (2,4)   out_proj_w
    const float* __restrict__ pw,     // (16,2)  proj_w
    const float* __restrict__ pb,     // (16,)   proj_b
    float* __restrict__ out)          // (64,16)
{
    __shared__ float s0[WPB][CHUNK];
    __shared__ float s1[WPB][CHUNK];

    const int w    = threadIdx.x >> 5;
    const int lane = threadIdx.x & 31;
    const int seq  = blockIdx.x * WPB + w;
    if (seq >= NSEQ) return;

    const int d = lane >> 3;   // inner-channel index 0..3
    const int s = lane & 7;    // state index 0..7

    // ---- per-lane constant weights ----
    const float ipx0 = ipw[d * 2 + 0];
    const float ipx1 = ipw[d * 2 + 1];
    const float ipz0 = ipw[(d + 4) * 2 + 0];
    const float ipz1 = ipw[(d + 4) * 2 + 1];
    const float cw0  = cw[d * 2 + 0];
    const float cw1  = cw[d * 2 + 1];
    const float cbd  = cb[d];
    const float xpd  = xpw[d];               // row 0: dt_rank contribution
    const float xpB  = xpw[(1 + s) * 4 + d]; // rows 1..8: B
    const float xpC  = xpw[(9 + s) * 4 + d]; // rows 9..16: C
    const float dtw  = dtw_[d];
    const float dtb  = dtb_[d];
    const float Ac   = -__expf(Alog[d * 8 + s]);   // A = -exp(A_log)

    float h = 0.f, acc = 0.f, sacc = 0.f, xprev = 0.f;

    const float* b0 = raw + (size_t)seq * (2 * TLEN);
    const float* b1 = b0 + TLEN;

    for (int c = 0; c < TLEN / CHUNK; ++c) {
        __syncwarp();
        if (lane < 16) {
            float4 v = *reinterpret_cast<const float4*>(b0 + c * CHUNK + lane * 4);
            *reinterpret_cast<float4*>(&s0[w][lane * 4]) = v;
        } else {
            float4 v = *reinterpret_cast<const float4*>(b1 + c * CHUNK + (lane - 16) * 4);
            *reinterpret_cast<float4*>(&s1[w][(lane - 16) * 4]) = v;
        }
        __syncwarp();

        #pragma unroll 8
        for (int tt = 0; tt < CHUNK; ++tt) {
            const float r0 = s0[w][tt];
            const float r1 = s1[w][tt];

            // in_proj -> x channel (own d), causal depthwise conv, silu
            const float xcur = fmaf(ipx1, r1, ipx0 * r0);
            const float cpre = fmaf(xprev, cw0, fmaf(xcur, cw1, cbd));
            xprev = xcur;
            const float xc = cpre * fast_sigmoid(cpre);

            // z gate (own d)
            const float zz = fmaf(ipz1, r1, ipz0 * r0);
            const float sz = zz * fast_sigmoid(zz);

            // distributed dot products over d: lanes l, l^8, l^16, l^24 share s
            float tB = xpB * xc;
            float tC = xpC * xc;
            float tD = xpd * xc;
            tB += __shfl_xor_sync(0xffffffffu, tB, 8);
            tC += __shfl_xor_sync(0xffffffffu, tC, 8);
            tD += __shfl_xor_sync(0xffffffffu, tD, 8);
            tB += __shfl_xor_sync(0xffffffffu, tB, 16);
            tC += __shfl_xor_sync(0xffffffffu, tC, 16);
            tD += __shfl_xor_sync(0xffffffffu, tD, 16);
            // tB = B[s], tC = C[s], tD = dt_raw (all lanes)

            // dt = softplus(dtw * dt_raw + dtb)  (numerically stable)
            const float u  = fmaf(dtw, tD, dtb);
            const float dt = fmaxf(u, 0.f) + __logf(1.f + __expf(-fabsf(u)));

            // diagonal SSM step
            const float a = __expf(dt * Ac);
            h = fmaf(a, h, dt * tB * xc);

            // fold silu(z) gate + mean-over-T linearity into accumulators
            acc  = fmaf(h, tC * sz, acc);
            sacc = fmaf(xc, sz, sacc);
        }
    }

    // ---- epilogue: y_sum[d] = sum_s acc + D_skip[d] * sacc ----
    float ya = acc;
    ya += __shfl_xor_sync(0xffffffffu, ya, 1);
    ya += __shfl_xor_sync(0xffffffffu, ya, 2);
    ya += __shfl_xor_sync(0xffffffffu, ya, 4);
    const float ysum = fmaf(Dskip[d], sacc, ya);

    // feat[c] = (1/T) * sum_d outw[c,d] * ysum[d]
    float f0 = outw[d] * ysum;
    float f1 = outw[4 + d] * ysum;
    f0 += __shfl_xor_sync(0xffffffffu, f0, 8);
    f1 += __shfl_xor_sync(0xffffffffu, f1, 8);
    f0 += __shfl_xor_sync(0xffffffffu, f0, 16);
    f1 += __shfl_xor_sync(0xffffffffu, f1, 16);
    f0 *= (1.0f / TLEN);
    f1 *= (1.0f / TLEN);

    // proj = relu(feat @ proj_w.T + proj_b), then mean over the 36 pairs
    if (lane < 16) {
        float p = fmaf(f0, pw[lane * 2 + 0], fmaf(f1, pw[lane * 2 + 1], pb[lane]));
        p = fmaxf(p, 0.f) * (1.0f / 36.0f);
        atomicAdd(&out[(seq / 36) * 16 + lane], p);
    }
}

extern "C" void kernel_launch(void* const* d_in, const int* in_sizes, int n_in,
                              void* d_out, int out_size) {
    const float* raw   = (const float*)d_in[0];
    const float* ipw   = (const float*)d_in[1];
    const float* cw    = (const float*)d_in[2];
    const float* cb    = (const float*)d_in[3];
    const float* xpw   = (const float*)d_in[4];
    const float* dtw   = (const float*)d_in[5];
    const float* dtb   = (const float*)d_in[6];
    const float* Alog  = (const float*)d_in[7];
    const float* Dsk   = (const float*)d_in[8];
    const float* outw  = (const float*)d_in[9];
    const float* pw    = (const float*)d_in[10];
    const float* pb    = (const float*)d_in[11];
    float* out = (float*)d_out;

    zero_out_kernel<<<(out_size + 255) / 256, 256>>>(out, out_size);

    const int grid = (NSEQ + WPB - 1) / WPB;   // 288 blocks of 8 warps
    mamba_fused_kernel<<<grid, BLOCK>>>(raw, ipw, cw, cb, xpw, dtw, dtb,
                                        Alog, Dsk, outw, pw, pb, out);
}